// round 1
// baseline (speedup 1.0000x reference)
#include <cuda_runtime.h>
#include <cuda_bf16.h>
#include <math.h>

// Problem constants
constexpr int Bq   = 4;
constexpr int Nq   = 64;
constexpr int Fq   = 64;
constexpr int FINq = 32;
constexpr int EDIMq= 32;
constexpr int FFq  = Fq * Fq;          // 4096
constexpr int ROWS = Bq * Nq;          // 256 target rows (b,n)

// Scratch (static device allocations are the sanctioned scratch mechanism)
__device__ float g_H[ROWS * Fq];                       // ping buffer for H
__device__ int   g_cnt[ROWS];                          // active edges per (b,n)
__device__ int   g_midx[ROWS * Nq];                    // compacted source index m
__device__ float g_Amat[(size_t)ROWS * Nq * FFq];      // compacted edge matrices (268MB, ~25% touched)

__device__ __forceinline__ float sigm(float x) { return 1.0f / (1.0f + expf(-x)); }

// ---------------------------------------------------------------------------
// Kernel 1: node embedding H0 = relu(X@W_embed + b) and per-row mask compaction
// grid = 256 blocks (one per (b,n)), 64 threads
// ---------------------------------------------------------------------------
__global__ __launch_bounds__(64) void k_embed(
    const float* __restrict__ X, const float* __restrict__ A,
    const float* __restrict__ W_embed, const float* __restrict__ b_embed,
    float* __restrict__ Hout)
{
    int row = blockIdx.x;            // b*64 + n
    int t = threadIdx.x;
    __shared__ float xs[FINq];
    if (t < FINq) xs[t] = X[row * FINq + t];
    __syncthreads();

    float acc = b_embed[t];
#pragma unroll
    for (int k = 0; k < FINq; k++) acc += xs[k] * W_embed[k * Fq + t];
    Hout[row * Fq + t] = fmaxf(acc, 0.0f);

    if (t == 0) {
        // A[b, n*64+m] == A[row*64 + m]
        const float* Arow = A + (size_t)row * Nq;
        int c = 0;
        for (int m = 0; m < Nq; m++)
            if (Arow[m] > 0.5f) g_midx[row * Nq + (c++)] = m;
        g_cnt[row] = c;
    }
}

// ---------------------------------------------------------------------------
// Kernel 2: edge matrices for ACTIVE edges only.
// Amat[slot][c] = relu(b_edge[c] + sum_e E[b, n*64+m, e] * W_edge[e, c])
// Each block: 2 target rows (their active edges) x 512 output columns.
// W_edge columns live in registers (2 cols/thread), E rows broadcast from smem.
// grid = (128 row-pairs, 8 col-chunks), 256 threads
// ---------------------------------------------------------------------------
__global__ __launch_bounds__(256) void k_edge(
    const float* __restrict__ E, const float* __restrict__ W_edge,
    const float* __restrict__ b_edge)
{
    int rp = blockIdx.x;             // row pair
    int c0 = blockIdx.y * 512;       // column chunk base
    int t  = threadIdx.x;

    __shared__ float Es[2 * Nq][EDIMq];
    __shared__ int   s_slot[2 * Nq];
    __shared__ int   s_ne;

    if (t == 0) {
        int ne = 0;
        for (int r = 0; r < 2; r++) {
            int row = rp * 2 + r;
            int cnt = g_cnt[row];
            for (int k = 0; k < cnt; k++) s_slot[ne++] = row * Nq + k;
        }
        s_ne = ne;
    }
    __syncthreads();
    int ne = s_ne;

    // load E rows for active edges: E index = (row*64 + m)*32 + e
    for (int i = t; i < ne * EDIMq; i += 256) {
        int kk = i >> 5, e = i & 31;
        int slot = s_slot[kk];
        int row  = slot >> 6;
        int m    = g_midx[slot];
        Es[kk][e] = E[((size_t)row * Nq + m) * EDIMq + e];
    }
    __syncthreads();

    // register-resident W columns (2 per thread), coalesced & L2-hot
    float w0[EDIMq], w1[EDIMq];
    int c_a = c0 + t, c_b = c0 + 256 + t;
#pragma unroll
    for (int e = 0; e < EDIMq; e++) {
        w0[e] = W_edge[e * FFq + c_a];
        w1[e] = W_edge[e * FFq + c_b];
    }
    float ba = b_edge[c_a], bb = b_edge[c_b];

    for (int kk = 0; kk < ne; kk++) {
        float a0 = ba, a1 = bb;
#pragma unroll
        for (int e = 0; e < EDIMq; e++) {
            float ev = Es[kk][e];
            a0 += ev * w0[e];
            a1 += ev * w1[e];
        }
        size_t base = (size_t)s_slot[kk] * FFq;
        g_Amat[base + c_a] = fmaxf(a0, 0.0f);
        g_Amat[base + c_b] = fmaxf(a1, 0.0f);
    }
}

// ---------------------------------------------------------------------------
// Kernel 3: one message-passing round, fused with the 2-step GRU.
// agg[i] = sum_k sum_j Amat[slot_k][i][j] * Hin[b, m_k, j]
// then  h1 = GRU(0, Hin[row]);  Hout[row] = GRU(h1, agg)
// grid = 256 blocks (one per (b,n)), 256 threads
// ---------------------------------------------------------------------------
__global__ __launch_bounds__(256) void k_round(
    const float* __restrict__ Hin, float* __restrict__ Hout,
    const float* __restrict__ gk, const float* __restrict__ grk,
    const float* __restrict__ gb, const float* __restrict__ grb)
{
    int row = blockIdx.x;            // b*64 + n
    int b = row >> 6;
    int t = threadIdx.x;

    __shared__ float Hs[Nq][Fq];     // source node states (16KB)
    __shared__ float agg[Fq];
    __shared__ float xold[Fq];
    __shared__ float xg[3 * Fq], hg[3 * Fq];
    __shared__ float h1[Fq];

    int cnt = g_cnt[row];

    for (int i = t; i < cnt * Fq; i += 256) {
        int kk = i >> 6, j = i & 63;
        int m = g_midx[row * Nq + kk];
        Hs[kk][j] = Hin[((size_t)b * Nq + m) * Fq + j];
    }
    if (t < Fq) xold[t] = Hin[(size_t)row * Fq + t];
    __syncthreads();

    // message aggregation: thread = i*4 + q, q covers 16 contiguous j's
    int i = t >> 2, q = t & 3;
    float acc = 0.0f;
    for (int kk = 0; kk < cnt; kk++) {
        const float4* Ar = reinterpret_cast<const float4*>(
            &g_Amat[((size_t)(row * Nq + kk)) * FFq + i * Fq + q * 16]);
        const float* hs = &Hs[kk][q * 16];
#pragma unroll
        for (int v = 0; v < 4; v++) {
            float4 a4 = Ar[v];
            acc += a4.x * hs[v * 4 + 0];
            acc += a4.y * hs[v * 4 + 1];
            acc += a4.z * hs[v * 4 + 2];
            acc += a4.w * hs[v * 4 + 3];
        }
    }
    acc += __shfl_xor_sync(0xffffffffu, acc, 1);
    acc += __shfl_xor_sync(0xffffffffu, acc, 2);
    if (q == 0) agg[i] = acc;
    __syncthreads();

    // GRU step 1: x = xold, h = 0  (so hg = recurrent bias only)
    if (t < 3 * Fq) {
        float a = gb[t];
#pragma unroll 8
        for (int j = 0; j < Fq; j++) a += xold[j] * gk[j * 192 + t];
        xg[t] = a;
        hg[t] = grb[t];
    }
    __syncthreads();
    if (t < Fq) {
        float z = sigm(xg[t] + hg[t]);
        float r = sigm(xg[Fq + t] + hg[Fq + t]);
        float cand = tanhf(xg[2 * Fq + t] + r * hg[2 * Fq + t]);
        h1[t] = (1.0f - z) * cand;    // h = 0
    }
    __syncthreads();

    // GRU step 2: x = agg, h = h1
    if (t < 3 * Fq) {
        float a = gb[t], hh = grb[t];
#pragma unroll 8
        for (int j = 0; j < Fq; j++) {
            a  += agg[j] * gk[j * 192 + t];
            hh += h1[j]  * grk[j * 192 + t];
        }
        xg[t] = a;
        hg[t] = hh;
    }
    __syncthreads();
    if (t < Fq) {
        float z = sigm(xg[t] + hg[t]);
        float r = sigm(xg[Fq + t] + hg[Fq + t]);
        float cand = tanhf(xg[2 * Fq + t] + r * hg[2 * Fq + t]);
        Hout[(size_t)row * Fq + t] = z * h1[t] + (1.0f - z) * cand;
    }
}

// ---------------------------------------------------------------------------
extern "C" void kernel_launch(void* const* d_in, const int* in_sizes, int n_in,
                              void* d_out, int out_size)
{
    const float* X       = (const float*)d_in[0];
    const float* A       = (const float*)d_in[1];
    const float* E       = (const float*)d_in[2];
    const float* W_embed = (const float*)d_in[3];
    const float* b_embed = (const float*)d_in[4];
    const float* W_edge  = (const float*)d_in[5];
    const float* b_edge  = (const float*)d_in[6];
    const float* gk      = (const float*)d_in[7];
    const float* grk     = (const float*)d_in[8];
    const float* gb      = (const float*)d_in[9];
    const float* grb     = (const float*)d_in[10];
    float* out = (float*)d_out;

    float* hbuf = nullptr;
    cudaGetSymbolAddress((void**)&hbuf, g_H);

    // H0 + mask compaction
    k_embed<<<ROWS, 64>>>(X, A, W_embed, b_embed, hbuf);
    // edge matrices for active edges
    k_edge<<<dim3(ROWS / 2, 8), 256>>>(E, W_edge, b_edge);
    // 3 rounds, ping-pong g_H <-> d_out, ending in d_out
    k_round<<<ROWS, 256>>>(hbuf, out,  gk, grk, gb, grb);
    k_round<<<ROWS, 256>>>(out,  hbuf, gk, grk, gb, grb);
    k_round<<<ROWS, 256>>>(hbuf, out,  gk, grk, gb, grb);
}

// round 2
// speedup vs baseline: 1.2684x; 1.2684x over previous
#include <cuda_runtime.h>
#include <cuda_bf16.h>
#include <math.h>

constexpr int Bq   = 4;
constexpr int Nq   = 64;
constexpr int Fq   = 64;
constexpr int FINq = 32;
constexpr int EDIMq= 32;
constexpr int FFq  = Fq * Fq;          // 4096
constexpr int ROWS = Bq * Nq;          // 256 target rows (b,n)

__device__ float g_H[ROWS * Fq];                       // ping buffer for H
__device__ int   g_cnt[ROWS];                          // active edges per (b,n)
__device__ int   g_midx[ROWS * Nq];                    // compacted source index m
__device__ float g_Amat[(size_t)ROWS * Nq * FFq];      // compacted edge matrices

__device__ __forceinline__ float sigm(float x) { return 1.0f / (1.0f + expf(-x)); }

__device__ __forceinline__ unsigned long long pack2(float lo, float hi) {
    unsigned long long r;
    asm("mov.b64 %0, {%1, %2};" : "=l"(r) : "f"(lo), "f"(hi));
    return r;
}
__device__ __forceinline__ void unpack2(unsigned long long v, float& lo, float& hi) {
    asm("mov.b64 {%0, %1}, %2;" : "=f"(lo), "=f"(hi) : "l"(v));
}
__device__ __forceinline__ unsigned long long ffma2(
    unsigned long long a, unsigned long long b, unsigned long long c) {
    unsigned long long d;
    asm("fma.rn.f32x2 %0, %1, %2, %3;" : "=l"(d) : "l"(a), "l"(b), "l"(c));
    return d;
}

// ---------------------------------------------------------------------------
// Kernel 1: H0 = relu(X@W_embed + b) and per-row mask compaction
// ---------------------------------------------------------------------------
__global__ __launch_bounds__(64) void k_embed(
    const float* __restrict__ X, const float* __restrict__ A,
    const float* __restrict__ W_embed, const float* __restrict__ b_embed,
    float* __restrict__ Hout)
{
    int row = blockIdx.x;
    int t = threadIdx.x;
    __shared__ float xs[FINq];
    if (t < FINq) xs[t] = X[row * FINq + t];
    __syncthreads();

    float acc = b_embed[t];
#pragma unroll
    for (int k = 0; k < FINq; k++) acc += xs[k] * W_embed[k * Fq + t];
    Hout[row * Fq + t] = fmaxf(acc, 0.0f);

    if (t == 0) {
        const float* Arow = A + (size_t)row * Nq;
        int c = 0;
        for (int m = 0; m < Nq; m++)
            if (Arow[m] > 0.5f) g_midx[row * Nq + (c++)] = m;
        g_cnt[row] = c;
    }
}

// ---------------------------------------------------------------------------
// Kernel 2: edge matrices for ACTIVE edges only, packed f32x2 FMA.
// Each block: 2 target rows x 512 output columns (2 cols/thread as a pair).
// ---------------------------------------------------------------------------
__global__ __launch_bounds__(256) void k_edge(
    const float* __restrict__ E, const float* __restrict__ W_edge,
    const float* __restrict__ b_edge)
{
    int rp = blockIdx.x;
    int c0 = blockIdx.y * 512;
    int t  = threadIdx.x;

    __shared__ unsigned long long Es2[2 * Nq][EDIMq];   // duplicated-pair E values (32KB)
    __shared__ int   s_slot[2 * Nq];
    __shared__ int   s_ne;

    if (t == 0) {
        int ne = 0;
        for (int r = 0; r < 2; r++) {
            int row = rp * 2 + r;
            int cnt = g_cnt[row];
            for (int k = 0; k < cnt; k++) s_slot[ne++] = row * Nq + k;
        }
        s_ne = ne;
    }
    __syncthreads();
    int ne = s_ne;

    for (int i = t; i < ne * EDIMq; i += 256) {
        int kk = i >> 5, e = i & 31;
        int slot = s_slot[kk];
        int row  = slot >> 6;
        int m    = g_midx[slot];
        float v  = E[((size_t)row * Nq + m) * EDIMq + e];
        Es2[kk][e] = pack2(v, v);
    }
    __syncthreads();

    // packed W column pair in registers
    unsigned long long w01[EDIMq];
    int c_a = c0 + t, c_b = c0 + 256 + t;
#pragma unroll
    for (int e = 0; e < EDIMq; e++)
        w01[e] = pack2(W_edge[e * FFq + c_a], W_edge[e * FFq + c_b]);
    unsigned long long bias01 = pack2(b_edge[c_a], b_edge[c_b]);

    int kk = 0;
    for (; kk + 2 <= ne; kk += 2) {
        unsigned long long acc0 = bias01, acc1 = bias01;
#pragma unroll
        for (int e = 0; e < EDIMq; e++) {
            acc0 = ffma2(Es2[kk][e],     w01[e], acc0);
            acc1 = ffma2(Es2[kk + 1][e], w01[e], acc1);
        }
        float a0, a1, b0v, b1v;
        unpack2(acc0, a0, a1);
        unpack2(acc1, b0v, b1v);
        size_t base0 = (size_t)s_slot[kk] * FFq;
        size_t base1 = (size_t)s_slot[kk + 1] * FFq;
        g_Amat[base0 + c_a] = fmaxf(a0, 0.0f);
        g_Amat[base0 + c_b] = fmaxf(a1, 0.0f);
        g_Amat[base1 + c_a] = fmaxf(b0v, 0.0f);
        g_Amat[base1 + c_b] = fmaxf(b1v, 0.0f);
    }
    if (kk < ne) {
        unsigned long long acc0 = bias01;
#pragma unroll
        for (int e = 0; e < EDIMq; e++)
            acc0 = ffma2(Es2[kk][e], w01[e], acc0);
        float a0, a1;
        unpack2(acc0, a0, a1);
        size_t base0 = (size_t)s_slot[kk] * FFq;
        g_Amat[base0 + c_a] = fmaxf(a0, 0.0f);
        g_Amat[base0 + c_b] = fmaxf(a1, 0.0f);
    }
}

// ---------------------------------------------------------------------------
// Kernel 3: one round (masked block-matvec + 2-step GRU), 1024 threads.
// thread = i*16 + q : output feature i (0..63), q covers 4 contiguous j's.
// Per edge each thread does ONE coalesced float4 load.
// ---------------------------------------------------------------------------
__global__ __launch_bounds__(1024) void k_round(
    const float* __restrict__ Hin, float* __restrict__ Hout,
    const float* __restrict__ gk, const float* __restrict__ grk,
    const float* __restrict__ gb, const float* __restrict__ grb)
{
    int row = blockIdx.x;
    int b = row >> 6;
    int t = threadIdx.x;

    __shared__ float4 Hs4[Nq][16];       // 16KB source states
    __shared__ float agg[Fq];
    __shared__ float xold[Fq];
    __shared__ float pg[2][4][3 * Fq];   // 6KB partial gate sums
    __shared__ float xg[3 * Fq], hg[3 * Fq];
    __shared__ float h1[Fq];

    int cnt = g_cnt[row];

    // load active source node states (vectorized, coalesced)
    for (int idx = t; idx < cnt * 16; idx += 1024) {
        int kk = idx >> 4, qq = idx & 15;
        int m = g_midx[row * Nq + kk];
        Hs4[kk][qq] = reinterpret_cast<const float4*>(Hin)[((size_t)b * Nq + m) * 16 + qq];
    }
    if (t < Fq) xold[t] = Hin[(size_t)row * Fq + t];
    __syncthreads();

    // ---- message aggregation ----
    int i = t >> 4, q = t & 15;
    const float4* Abase = reinterpret_cast<const float4*>(g_Amat)
                        + (size_t)row * Nq * (FFq / 4) + i * 16 + q;
    float acc = 0.0f;
    int kk = 0;
    for (; kk + 4 <= cnt; kk += 4) {
        float4 a0 = Abase[(size_t)(kk + 0) * (FFq / 4)];
        float4 a1 = Abase[(size_t)(kk + 1) * (FFq / 4)];
        float4 a2 = Abase[(size_t)(kk + 2) * (FFq / 4)];
        float4 a3 = Abase[(size_t)(kk + 3) * (FFq / 4)];
        float4 h0 = Hs4[kk + 0][q];
        float4 h1v= Hs4[kk + 1][q];
        float4 h2 = Hs4[kk + 2][q];
        float4 h3 = Hs4[kk + 3][q];
        acc += a0.x*h0.x + a0.y*h0.y + a0.z*h0.z + a0.w*h0.w;
        acc += a1.x*h1v.x + a1.y*h1v.y + a1.z*h1v.z + a1.w*h1v.w;
        acc += a2.x*h2.x + a2.y*h2.y + a2.z*h2.z + a2.w*h2.w;
        acc += a3.x*h3.x + a3.y*h3.y + a3.z*h3.z + a3.w*h3.w;
    }
    for (; kk < cnt; kk++) {
        float4 a0 = Abase[(size_t)kk * (FFq / 4)];
        float4 h0 = Hs4[kk][q];
        acc += a0.x*h0.x + a0.y*h0.y + a0.z*h0.z + a0.w*h0.w;
    }
    acc += __shfl_xor_sync(0xffffffffu, acc, 1);
    acc += __shfl_xor_sync(0xffffffffu, acc, 2);
    acc += __shfl_xor_sync(0xffffffffu, acc, 4);
    acc += __shfl_xor_sync(0xffffffffu, acc, 8);
    if (q == 0) agg[i] = acc;
    __syncthreads();

    // ---- GRU step 1: x = xold, h = 0 (hg = recurrent bias only) ----
    if (t < 768) {
        int o = t % 192, s = t / 192;
        float a = 0.0f;
#pragma unroll
        for (int j = s * 16; j < s * 16 + 16; j++) a += xold[j] * gk[j * 192 + o];
        pg[0][s][o] = a;
    }
    __syncthreads();
    if (t < 192)
        xg[t] = gb[t] + pg[0][0][t] + pg[0][1][t] + pg[0][2][t] + pg[0][3][t];
    __syncthreads();
    if (t < Fq) {
        float z = sigm(xg[t] + grb[t]);
        float r = sigm(xg[Fq + t] + grb[Fq + t]);
        float cand = tanhf(xg[2 * Fq + t] + r * grb[2 * Fq + t]);
        h1[t] = (1.0f - z) * cand;
    }
    __syncthreads();

    // ---- GRU step 2: x = agg, h = h1 ----
    if (t < 768) {
        int o = t % 192, s = t / 192;
        float a = 0.0f, hh = 0.0f;
#pragma unroll
        for (int j = s * 16; j < s * 16 + 16; j++) {
            a  += agg[j] * gk[j * 192 + o];
            hh += h1[j]  * grk[j * 192 + o];
        }
        pg[0][s][o] = a;
        pg[1][s][o] = hh;
    }
    __syncthreads();
    if (t < 192) {
        xg[t] = gb[t]  + pg[0][0][t] + pg[0][1][t] + pg[0][2][t] + pg[0][3][t];
        hg[t] = grb[t] + pg[1][0][t] + pg[1][1][t] + pg[1][2][t] + pg[1][3][t];
    }
    __syncthreads();
    if (t < Fq) {
        float z = sigm(xg[t] + hg[t]);
        float r = sigm(xg[Fq + t] + hg[Fq + t]);
        float cand = tanhf(xg[2 * Fq + t] + r * hg[2 * Fq + t]);
        Hout[(size_t)row * Fq + t] = z * h1[t] + (1.0f - z) * cand;
    }
}

// ---------------------------------------------------------------------------
extern "C" void kernel_launch(void* const* d_in, const int* in_sizes, int n_in,
                              void* d_out, int out_size)
{
    const float* X       = (const float*)d_in[0];
    const float* A       = (const float*)d_in[1];
    const float* E       = (const float*)d_in[2];
    const float* W_embed = (const float*)d_in[3];
    const float* b_embed = (const float*)d_in[4];
    const float* W_edge  = (const float*)d_in[5];
    const float* b_edge  = (const float*)d_in[6];
    const float* gk      = (const float*)d_in[7];
    const float* grk     = (const float*)d_in[8];
    const float* gb      = (const float*)d_in[9];
    const float* grb     = (const float*)d_in[10];
    float* out = (float*)d_out;

    float* hbuf = nullptr;
    cudaGetSymbolAddress((void**)&hbuf, g_H);

    k_embed<<<ROWS, 64>>>(X, A, W_embed, b_embed, hbuf);
    k_edge<<<dim3(ROWS / 2, 8), 256>>>(E, W_edge, b_edge);
    k_round<<<ROWS, 1024>>>(hbuf, out,  gk, grk, gb, grb);
    k_round<<<ROWS, 1024>>>(out,  hbuf, gk, grk, gb, grb);
    k_round<<<ROWS, 1024>>>(hbuf, out,  gk, grk, gb, grb);
}

// round 3
// speedup vs baseline: 1.3811x; 1.0889x over previous
#include <cuda_runtime.h>
#include <cuda_fp16.h>
#include <math.h>

constexpr int Bq   = 4;
constexpr int Nq   = 64;
constexpr int Fq   = 64;
constexpr int FINq = 32;
constexpr int EDIMq= 32;
constexpr int FFq  = Fq * Fq;          // 4096
constexpr int ROWS = Bq * Nq;          // 256 target rows (b,n)

__device__ float  g_H[ROWS * Fq];                      // ping buffer for H
__device__ int    g_cnt[ROWS];                         // active edges per (b,n)
__device__ int    g_midx[ROWS * Nq];                   // compacted source index m
__device__ __half g_Amat[(size_t)ROWS * Nq * FFq];     // compacted edge matrices (fp16, 134MB)

__device__ __forceinline__ float sigm(float x) { return 1.0f / (1.0f + expf(-x)); }

__device__ __forceinline__ unsigned long long pack2(float lo, float hi) {
    unsigned long long r;
    asm("mov.b64 %0, {%1, %2};" : "=l"(r) : "f"(lo), "f"(hi));
    return r;
}
__device__ __forceinline__ void unpack2(unsigned long long v, float& lo, float& hi) {
    asm("mov.b64 {%0, %1}, %2;" : "=f"(lo), "=f"(hi) : "l"(v));
}
__device__ __forceinline__ unsigned long long ffma2(
    unsigned long long a, unsigned long long b, unsigned long long c) {
    unsigned long long d;
    asm("fma.rn.f32x2 %0, %1, %2, %3;" : "=l"(d) : "l"(a), "l"(b), "l"(c));
    return d;
}

// ---------------------------------------------------------------------------
// Kernel 1: H0 = relu(X@W_embed + b) and per-row mask compaction
// ---------------------------------------------------------------------------
__global__ __launch_bounds__(64) void k_embed(
    const float* __restrict__ X, const float* __restrict__ A,
    const float* __restrict__ W_embed, const float* __restrict__ b_embed,
    float* __restrict__ Hout)
{
    int row = blockIdx.x;
    int t = threadIdx.x;
    __shared__ float xs[FINq];
    if (t < FINq) xs[t] = X[row * FINq + t];
    __syncthreads();

    float acc = b_embed[t];
#pragma unroll
    for (int k = 0; k < FINq; k++) acc += xs[k] * W_embed[k * Fq + t];
    Hout[row * Fq + t] = fmaxf(acc, 0.0f);

    if (t == 0) {
        const float* Arow = A + (size_t)row * Nq;
        int c = 0;
        for (int m = 0; m < Nq; m++)
            if (Arow[m] > 0.5f) g_midx[row * Nq + (c++)] = m;
        g_cnt[row] = c;
    }
}

// ---------------------------------------------------------------------------
// Kernel 2: edge matrices for ACTIVE edges only, packed f32x2 FMA, fp16 out.
// Each block: 2 target rows x 512 output columns.
// Thread t handles ADJACENT column pair (c0+2t, c0+2t+1) -> one half2 store.
// ---------------------------------------------------------------------------
__global__ __launch_bounds__(256) void k_edge(
    const float* __restrict__ E, const float* __restrict__ W_edge,
    const float* __restrict__ b_edge)
{
    int rp = blockIdx.x;
    int c0 = blockIdx.y * 512;
    int t  = threadIdx.x;

    __shared__ unsigned long long Es2[2 * Nq][EDIMq];   // duplicated-pair E values (32KB)
    __shared__ int   s_slot[2 * Nq];
    __shared__ int   s_ne;

    if (t == 0) {
        int ne = 0;
        for (int r = 0; r < 2; r++) {
            int row = rp * 2 + r;
            int cnt = g_cnt[row];
            for (int k = 0; k < cnt; k++) s_slot[ne++] = row * Nq + k;
        }
        s_ne = ne;
    }
    __syncthreads();
    int ne = s_ne;

    for (int i = t; i < ne * EDIMq; i += 256) {
        int kk = i >> 5, e = i & 31;
        int slot = s_slot[kk];
        int row  = slot >> 6;
        int m    = g_midx[slot];
        float v  = E[((size_t)row * Nq + m) * EDIMq + e];
        Es2[kk][e] = pack2(v, v);
    }
    __syncthreads();

    // adjacent packed W column pair in registers (float2 loads)
    int cp = c0 + 2 * t;
    unsigned long long w01[EDIMq];
#pragma unroll
    for (int e = 0; e < EDIMq; e++) {
        float2 wv = reinterpret_cast<const float2*>(W_edge + (size_t)e * FFq + cp)[0];
        w01[e] = pack2(wv.x, wv.y);
    }
    float2 bv = reinterpret_cast<const float2*>(b_edge + cp)[0];
    unsigned long long bias01 = pack2(bv.x, bv.y);

    __half2* Aout = reinterpret_cast<__half2*>(g_Amat);
    int cidx = cp >> 1;   // half2 index within a 4096-col row

    int kk = 0;
    for (; kk + 2 <= ne; kk += 2) {
        unsigned long long acc0 = bias01, acc1 = bias01;
#pragma unroll
        for (int e = 0; e < EDIMq; e++) {
            acc0 = ffma2(Es2[kk][e],     w01[e], acc0);
            acc1 = ffma2(Es2[kk + 1][e], w01[e], acc1);
        }
        float a0, a1, b0v, b1v;
        unpack2(acc0, a0, a1);
        unpack2(acc1, b0v, b1v);
        Aout[(size_t)s_slot[kk]     * (FFq / 2) + cidx] =
            __floats2half2_rn(fmaxf(a0, 0.0f), fmaxf(a1, 0.0f));
        Aout[(size_t)s_slot[kk + 1] * (FFq / 2) + cidx] =
            __floats2half2_rn(fmaxf(b0v, 0.0f), fmaxf(b1v, 0.0f));
    }
    if (kk < ne) {
        unsigned long long acc0 = bias01;
#pragma unroll
        for (int e = 0; e < EDIMq; e++)
            acc0 = ffma2(Es2[kk][e], w01[e], acc0);
        float a0, a1;
        unpack2(acc0, a0, a1);
        Aout[(size_t)s_slot[kk] * (FFq / 2) + cidx] =
            __floats2half2_rn(fmaxf(a0, 0.0f), fmaxf(a1, 0.0f));
    }
}

// ---------------------------------------------------------------------------
// Kernel 3: one round (masked block-matvec + 2-step GRU), 1024 threads.
// thread = i*16 + q : output feature i (0..63), q covers 4 contiguous j's.
// Per edge each thread does ONE coalesced 8B (4xfp16) load; math in fp32.
// ---------------------------------------------------------------------------
__global__ __launch_bounds__(1024) void k_round(
    const float* __restrict__ Hin, float* __restrict__ Hout,
    const float* __restrict__ gk, const float* __restrict__ grk,
    const float* __restrict__ gb, const float* __restrict__ grb)
{
    int row = blockIdx.x;
    int b = row >> 6;
    int t = threadIdx.x;

    __shared__ float4 Hs4[Nq][16];       // 16KB source states
    __shared__ float agg[Fq];
    __shared__ float xold[Fq];
    __shared__ float pg[2][4][3 * Fq];   // 6KB partial gate sums
    __shared__ float xg[3 * Fq], hg[3 * Fq];
    __shared__ float h1[Fq];

    int cnt = g_cnt[row];

    for (int idx = t; idx < cnt * 16; idx += 1024) {
        int kk = idx >> 4, qq = idx & 15;
        int m = g_midx[row * Nq + kk];
        Hs4[kk][qq] = reinterpret_cast<const float4*>(Hin)[((size_t)b * Nq + m) * 16 + qq];
    }
    if (t < Fq) xold[t] = Hin[(size_t)row * Fq + t];
    __syncthreads();

    // ---- message aggregation (fp16 Amat, fp32 accumulate) ----
    int i = t >> 4, q = t & 15;
    // each thread reads 4 halves = one uint2 per edge
    const uint2* Abase = reinterpret_cast<const uint2*>(g_Amat)
                       + (size_t)row * Nq * (FFq / 4) + i * 16 + q;
    float acc = 0.0f;

    auto dot4 = [&](uint2 a, const float4& h) {
        __half2 p0 = *reinterpret_cast<__half2*>(&a.x);
        __half2 p1 = *reinterpret_cast<__half2*>(&a.y);
        float2 f0 = __half22float2(p0);
        float2 f1 = __half22float2(p1);
        return f0.x * h.x + f0.y * h.y + f1.x * h.z + f1.y * h.w;
    };

    int kk = 0;
    for (; kk + 4 <= cnt; kk += 4) {
        uint2 a0 = Abase[(size_t)(kk + 0) * (FFq / 4)];
        uint2 a1 = Abase[(size_t)(kk + 1) * (FFq / 4)];
        uint2 a2 = Abase[(size_t)(kk + 2) * (FFq / 4)];
        uint2 a3 = Abase[(size_t)(kk + 3) * (FFq / 4)];
        acc += dot4(a0, Hs4[kk + 0][q]);
        acc += dot4(a1, Hs4[kk + 1][q]);
        acc += dot4(a2, Hs4[kk + 2][q]);
        acc += dot4(a3, Hs4[kk + 3][q]);
    }
    for (; kk < cnt; kk++)
        acc += dot4(Abase[(size_t)kk * (FFq / 4)], Hs4[kk][q]);

    acc += __shfl_xor_sync(0xffffffffu, acc, 1);
    acc += __shfl_xor_sync(0xffffffffu, acc, 2);
    acc += __shfl_xor_sync(0xffffffffu, acc, 4);
    acc += __shfl_xor_sync(0xffffffffu, acc, 8);
    if (q == 0) agg[i] = acc;
    __syncthreads();

    // ---- GRU step 1: x = xold, h = 0 (hg = recurrent bias only) ----
    if (t < 768) {
        int o = t % 192, s = t / 192;
        float a = 0.0f;
#pragma unroll
        for (int j = s * 16; j < s * 16 + 16; j++) a += xold[j] * gk[j * 192 + o];
        pg[0][s][o] = a;
    }
    __syncthreads();
    if (t < 192)
        xg[t] = gb[t] + pg[0][0][t] + pg[0][1][t] + pg[0][2][t] + pg[0][3][t];
    __syncthreads();
    if (t < Fq) {
        float z = sigm(xg[t] + grb[t]);
        float r = sigm(xg[Fq + t] + grb[Fq + t]);
        float cand = tanhf(xg[2 * Fq + t] + r * grb[2 * Fq + t]);
        h1[t] = (1.0f - z) * cand;
    }
    __syncthreads();

    // ---- GRU step 2: x = agg, h = h1 ----
    if (t < 768) {
        int o = t % 192, s = t / 192;
        float a = 0.0f, hh = 0.0f;
#pragma unroll
        for (int j = s * 16; j < s * 16 + 16; j++) {
            a  += agg[j] * gk[j * 192 + o];
            hh += h1[j]  * grk[j * 192 + o];
        }
        pg[0][s][o] = a;
        pg[1][s][o] = hh;
    }
    __syncthreads();
    if (t < 192) {
        xg[t] = gb[t]  + pg[0][0][t] + pg[0][1][t] + pg[0][2][t] + pg[0][3][t];
        hg[t] = grb[t] + pg[1][0][t] + pg[1][1][t] + pg[1][2][t] + pg[1][3][t];
    }
    __syncthreads();
    if (t < Fq) {
        float z = sigm(xg[t] + hg[t]);
        float r = sigm(xg[Fq + t] + hg[Fq + t]);
        float cand = tanhf(xg[2 * Fq + t] + r * hg[2 * Fq + t]);
        Hout[(size_t)row * Fq + t] = z * h1[t] + (1.0f - z) * cand;
    }
}

// ---------------------------------------------------------------------------
extern "C" void kernel_launch(void* const* d_in, const int* in_sizes, int n_in,
                              void* d_out, int out_size)
{
    const float* X       = (const float*)d_in[0];
    const float* A       = (const float*)d_in[1];
    const float* E       = (const float*)d_in[2];
    const float* W_embed = (const float*)d_in[3];
    const float* b_embed = (const float*)d_in[4];
    const float* W_edge  = (const float*)d_in[5];
    const float* b_edge  = (const float*)d_in[6];
    const float* gk      = (const float*)d_in[7];
    const float* grk     = (const float*)d_in[8];
    const float* gb      = (const float*)d_in[9];
    const float* grb     = (const float*)d_in[10];
    float* out = (float*)d_out;

    float* hbuf = nullptr;
    cudaGetSymbolAddress((void**)&hbuf, g_H);

    k_embed<<<ROWS, 64>>>(X, A, W_embed, b_embed, hbuf);
    k_edge<<<dim3(ROWS / 2, 8), 256>>>(E, W_edge, b_edge);
    k_round<<<ROWS, 1024>>>(hbuf, out,  gk, grk, gb, grb);
    k_round<<<ROWS, 1024>>>(out,  hbuf, gk, grk, gb, grb);
    k_round<<<ROWS, 1024>>>(hbuf, out,  gk, grk, gb, grb);
}